// round 11
// baseline (speedup 1.0000x reference)
#include <cuda_runtime.h>
#include <cstdint>

// SlidingWindowCmn (16, 60000, 80) fp32, window=600, min=100, center=False,
// norm_vars=True.
// TMA 1D bulk load (tid0 + mbarrier) -> 704-row SMEM ring (+8 mirror) ->
// per-thread sliding window (1 thread/feature). 32-row groups, lead = 2
// groups; one __syncthreads per group; issue strictly after consume so
// overwritten slots (last vo-read in group g-1) are dead for all threads.

namespace {
constexpr int kB      = 16;
constexpr int kT      = 60000;
constexpr int kF      = 80;
constexpr int kWin    = 600;
constexpr int kMin    = 100;
constexpr int kChunks = 9;
constexpr int kL      = 6656;               // 8*6656 + 6752 = 60000 (32-mult)
constexpr int kRL     = 704;                // logical ring rows (mult of 32)
constexpr int kRLf    = kRL * kF;           // 56320 floats
constexpr uint32_t kRLb = kRL * 320u;       // 225280 bytes (logical)
constexpr int kMirRows = 8;                 // mirror rows (7 needed)
constexpr int kMbF    = 32;                 // 128 B mbar area (4 mbars + pad)
constexpr uint32_t kSmemB = (uint32_t)(kMbF + kRLf + kMirRows * kF) * 4u; // 227968
constexpr int kVOf    = (kRL - kWin - 1) * kF;  // 103 rows -> 8240 floats
constexpr float kInvW = 1.0f / 601.0f;
constexpr int kGrid   = kB * kChunks;       // 144
constexpr int kGRows  = 32;                 // rows per group
constexpr int kGf     = kGRows * kF;        // 2560 floats
constexpr uint32_t kGB = kGRows * 320u;     // 10240 bytes
}

__device__ __forceinline__ uint32_t smem_u32(const void* p) {
    uint32_t a;
    asm("{ .reg .u64 t; cvta.to.shared.u64 t, %1; cvt.u32.u64 %0, t; }"
        : "=r"(a) : "l"(p));
    return a;
}
__device__ __forceinline__ void mbar_init(uint32_t mb) {
    asm volatile("mbarrier.init.shared.b64 [%0], 1;" :: "r"(mb) : "memory");
}
__device__ __forceinline__ void mbar_expect(uint32_t mb, uint32_t bytes) {
    asm volatile("mbarrier.arrive.expect_tx.shared.b64 _, [%0], %1;"
                 :: "r"(mb), "r"(bytes) : "memory");
}
__device__ __forceinline__ void bulk_ld(uint32_t dst, const float* src,
                                        uint32_t bytes, uint32_t mb) {
    asm volatile(
        "cp.async.bulk.shared::cta.global.mbarrier::complete_tx::bytes "
        "[%0], [%1], %2, [%3];"
        :: "r"(dst), "l"(src), "r"(bytes), "r"(mb) : "memory");
}
__device__ __forceinline__ void mbar_wait(uint32_t mb, uint32_t ph) {
    asm volatile(
        "{\n\t.reg .pred P;\n\t"
        "W%=: mbarrier.try_wait.parity.acquire.cta.shared::cta.b64 P, [%0], %1, 0x989680;\n\t"
        "@P bra D%=;\n\t"
        "bra W%=;\n\t"
        "D%=:\n\t}"
        :: "r"(mb), "r"(ph) : "memory");
}

__global__ void __launch_bounds__(kF, 1)
cmn_kernel(const float* __restrict__ x, float* __restrict__ out)
{
    extern __shared__ float smem[];
    float* ring = smem + kMbF;

    const int f = threadIdx.x;                    // feature 0..79
    const int c = blockIdx.x % kChunks;
    const int b = blockIdx.x / kChunks;

    const float* xb = x + (size_t)b * kT * kF;
    const int start = c * kL;
    const int end   = (c == kChunks - 1) ? kT : start + kL;

    const uint32_t mbb = smem_u32(smem);          // 4 mbarriers at smem[0..7]
    const uint32_t rsb = smem_u32(ring);
    const float* pClamp = x + ((size_t)kB * kT - kGRows) * kF;

    if (f == 0) {
        mbar_init(mbb);      mbar_init(mbb + 8);
        mbar_init(mbb + 16); mbar_init(mbb + 24);
    }
    __syncthreads();

    int vnF;                  // consume group float-offset (slot*80)
    uint32_t issB;            // issue group byte-offset in ring
    const float* pIss;        // issue group global base
    if (c == 0) {
        vnF = 0; issB = 0; pIss = xb;
    } else {
        const int t0   = start - 608;             // 32-aligned: 7 pad + 601 warmup
        const int slot = t0 % kRL;                // multiple of 32
        vnF = slot * kF; issB = (uint32_t)slot * 320u;
        pIss = xb + (size_t)t0 * kF;
    }

    int ic = 0;               // issue-group counter
    int gc = 0;               // consume-group counter

    auto issueG = [&]() {
        if (f == 0) {
            const float* q = (pIss > pClamp) ? pClamp : pIss;
            const uint32_t mb = mbb + (uint32_t)((ic & 3) << 3);
            const uint32_t extra = (issB == 0) ? 2240u : 0u;  // mirror 7 rows
            mbar_expect(mb, kGB + extra);
            bulk_ld(rsb + issB, q, kGB, mb);
            if (extra) bulk_ld(rsb + kRLb, q, extra, mb);
        }
        pIss += kGf;
        issB += kGB; if (issB == kRLb) issB = 0;
        ++ic;
    };
    auto waitG = [&]() {
        if (f == 0)
            mbar_wait(mbb + (uint32_t)((gc & 3) << 3), (uint32_t)((gc >> 2) & 1));
        __syncthreads();
        ++gc;
    };

    issueG(); issueG();       // prologue: lead = 2 groups (64 rows)

    float s = 0.f, ss = 0.f, mean = 0.f, qss = 0.f;
    float* po = out + (size_t)b * kT * kF + f;
    int nSteady;

    if (c == 0) {
        // groups 0..2: rows 0..95 accumulate
        #pragma unroll 1
        for (int g = 0; g < 3; ++g) {
            waitG();
            const float* rv = ring + vnF + f;
            #pragma unroll
            for (int u = 0; u < kGRows; ++u) {
                float v = rv[u * kF]; s += v; ss = __fmaf_rn(v, v, ss);
            }
            vnF += kGf; issueG();
        }
        // group 3: rows 96..127
        {
            waitG();
            const float* rv = ring + vnF + f;
            #pragma unroll
            for (int u = 0; u < 4; ++u) {          // rows 96..99
                float v = rv[u * kF]; s += v; ss = __fmaf_rn(v, v, ss);
            }
            const float inv = 1.0f / (float)kMin;  // burst rows 0..99
            const float m0  = s * inv;
            const float vr0 = __fmaf_rn(-m0, m0, ss * inv);
            const float rs0 = rsqrtf(vr0);
            #pragma unroll 4
            for (int t = 0; t < kMin; ++t) {
                float v = ring[t * kF + f];
                __stcs(po + t * kF, (v - m0) * rs0);
            }
            float n = 100.0f;
            #pragma unroll
            for (int u = 4; u < kGRows; ++u) {     // rows 100..127 growing
                float v = rv[u * kF]; s += v; ss = __fmaf_rn(v, v, ss);
                n += 1.0f;
                float inv2 = __fdividef(1.0f, n);
                float m    = s * inv2;
                float var  = __fmaf_rn(-m, m, ss * inv2);
                __stcs(po + (96 + u) * kF, (v - m) * rsqrtf(var));
            }
            vnF += kGf; issueG();
        }
        // groups 4..17: rows 128..575 growing
        po += 128 * kF;
        float n = 128.0f;
        #pragma unroll 1
        for (int g = 4; g < 18; ++g) {
            waitG();
            const float* rv = ring + vnF + f;
            #pragma unroll
            for (int u = 0; u < kGRows; ++u) {
                float v = rv[u * kF]; s += v; ss = __fmaf_rn(v, v, ss);
                n += 1.0f;
                float inv = __fdividef(1.0f, n);
                float m   = s * inv;
                float var = __fmaf_rn(-m, m, ss * inv);
                __stcs(po + u * kF, (v - m) * rsqrtf(var));
            }
            vnF += kGf; po += kGf; issueG();
        }
        // group 18: rows 576..607 (transition at t=600)
        {
            waitG();
            const float* rv = ring + vnF + f;
            #pragma unroll
            for (int u = 0; u < 24; ++u) {         // rows 576..599 growing
                float v = rv[u * kF]; s += v; ss = __fmaf_rn(v, v, ss);
                n += 1.0f;
                float inv = __fdividef(1.0f, n);
                float m   = s * inv;
                float var = __fmaf_rn(-m, m, ss * inv);
                __stcs(po + u * kF, (v - m) * rsqrtf(var));
            }
            mean = s * kInvW; qss = ss * kInvW;
            #pragma unroll
            for (int u = 24; u < kGRows; ++u) {    // rows 600..607 steady-1
                float vn = rv[u * kF];
                float vo = (u == 24) ? 0.0f : ring[(u - 25) * kF + f];
                float t1 = (vn - vo) * kInvW;
                mean += t1;
                qss   = __fmaf_rn(t1, vn + vo, qss);
                float var = __fmaf_rn(-mean, mean, qss);
                __stcs(po + u * kF, (vn - mean) * rsqrtf(var));
            }
            vnF += kGf; issueG();                  // vnF = 608*kF
        }
        nSteady = (kL - 608) / kGRows;             // 189
    } else {
        // warmup group 0: rows t0+7 .. t0+31 (start-601 .. start-577)
        {
            waitG();
            const float* rv = ring + vnF + f;
            #pragma unroll
            for (int u = 7; u < kGRows; ++u) {
                float v = rv[u * kF]; s += v; ss = __fmaf_rn(v, v, ss);
            }
            vnF += kGf; if (vnF == kRLf) vnF = 0;
            issueG();
        }
        // warmup groups 1..18: 576 rows
        #pragma unroll 1
        for (int g = 1; g < 19; ++g) {
            waitG();
            const float* rv = ring + vnF + f;
            #pragma unroll
            for (int u = 0; u < kGRows; ++u) {
                float v = rv[u * kF]; s += v; ss = __fmaf_rn(v, v, ss);
            }
            vnF += kGf; if (vnF == kRLf) vnF = 0;
            issueG();
        }
        mean = s * kInvW; qss = ss * kInvW;
        nSteady = (end - start) / kGRows;          // 208 or 211
    }

    // ---- steady sliding loop ----
    const int g0row = (c == 0) ? 608 : start;
    float* po2 = out + (size_t)b * kT * kF + (size_t)g0row * kF + f;
    #pragma unroll 1
    for (int g = 0; g < nSteady; ++g) {
        waitG();
        const float* rvn = ring + vnF + f;
        int voF = vnF + kVOf;                      // slot (t-601), group-aligned
        if (voF >= kRLf) voF -= kRLf;              // one wrap check / 32 rows
        const float* rvo = ring + voF + f;         // mirror covers straddle
        #pragma unroll
        for (int u = 0; u < kGRows; ++u) {
            float vn = rvn[u * kF];
            float vo = rvo[u * kF];
            float t1 = (vn - vo) * kInvW;
            mean += t1;
            qss   = __fmaf_rn(t1, vn + vo, qss);
            float var = __fmaf_rn(-mean, mean, qss);
            __stcs(po2 + u * kF, (vn - mean) * rsqrtf(var));
        }
        vnF += kGf; if (vnF == kRLf) vnF = 0;
        po2 += kGf;
        issueG();
    }
}

extern "C" void kernel_launch(void* const* d_in, const int* in_sizes, int n_in,
                              void* d_out, int out_size)
{
    const float* x = (const float*)d_in[0];
    float* o = (float*)d_out;
    (void)in_sizes; (void)n_in; (void)out_size;

    cudaFuncSetAttribute(cmn_kernel,
                         cudaFuncAttributeMaxDynamicSharedMemorySize, (int)kSmemB);
    cmn_kernel<<<kGrid, kF, kSmemB>>>(x, o);
}

// round 12
// speedup vs baseline: 1.0289x; 1.0289x over previous
#include <cuda_runtime.h>
#include <cstdint>

// SlidingWindowCmn (16, 60000, 80) fp32, window=600, min=100, center=False,
// norm_vars=True.
// Distributed 16B cp.async (8-row subcommits) -> 704-row SMEM ring (+8
// mirror) -> per-thread sliding window (1 thread/feature). 32-row consume
// groups with one wait_group+__syncthreads each; lead = 64 rows (8
// subcommits, wait_group 4). Cross-thread overwrite safety: writes in
// iteration g hit slot-rows R-640..R-609, vo reads R-601..R-570 (disjoint).

namespace {
constexpr int kB      = 16;
constexpr int kT      = 60000;
constexpr int kF      = 80;
constexpr int kWin    = 600;
constexpr int kMin    = 100;
constexpr int kChunks = 9;
constexpr int kL      = 6656;               // 8*6656 + 6752 = 60000 (32-mult)
constexpr int kRL     = 704;                // logical ring rows (mult of 32)
constexpr int kRLf    = kRL * kF;           // 56320 floats
constexpr uint32_t kRLb = kRL * 320u;       // 225280 bytes (logical)
constexpr uint32_t kSmemB = (kRL + 8) * 320u;   // 227840 bytes (+ 8 mirror)
constexpr int kVOf    = (kRL - kWin - 1) * kF;  // 103 rows -> 8240 floats
constexpr float kInvW = 1.0f / 601.0f;
constexpr int kGrid   = kB * kChunks;       // 144
constexpr int kGR     = 32;                 // consume rows per group
constexpr int kGf     = kGR * kF;           // 2560 floats
}

__device__ __forceinline__ uint32_t smem_u32(const void* p) {
    uint32_t a;
    asm("{ .reg .u64 t; cvta.to.shared.u64 t, %1; cvt.u32.u64 %0, t; }"
        : "=r"(a) : "l"(p));
    return a;
}
__device__ __forceinline__ void cpa16(uint32_t s, const float* g) {
    asm volatile("cp.async.cg.shared.global [%0], [%1], 16;" :: "r"(s), "l"(g));
}
__device__ __forceinline__ void cpcommit() {
    asm volatile("cp.async.commit_group;" ::: "memory");
}
__device__ __forceinline__ void cpwait4() {
    asm volatile("cp.async.wait_group 4;" ::: "memory");
}

__global__ void __launch_bounds__(kF, 1)
cmn_kernel(const float* __restrict__ x, float* __restrict__ out)
{
    extern __shared__ float ring[];
    const int f = threadIdx.x;                    // feature 0..79
    const int c = blockIdx.x % kChunks;
    const int b = blockIdx.x / kChunks;

    const float* xb = x + (size_t)b * kT * kF;
    const int start = c * kL;
    const int end   = (c == kChunks - 1) ? kT : start + kL;

    const uint32_t rsb = smem_u32(ring);
    const float* pClamp = x + ((size_t)kB * kT - 8) * kF;   // last 8-row block

    int vnF;                  // consume group float-offset (slot*80)
    uint32_t issB;            // issue subcommit byte-offset (8-row grain)
    const float* pIss;
    if (c == 0) {
        vnF = 0; issB = 0; pIss = xb;
    } else {
        const int t0   = start - 608;             // 32-aligned: 7 pad + 601 warmup
        const int slot = t0 % kRL;                // multiple of 32
        vnF = slot * kF; issB = (uint32_t)slot * 320u;
        pIss = xb + (size_t)t0 * kF;
    }

    // 8-row subcommit: 2560 B, 32 B per thread (2 x 16B)
    auto issue8 = [&]() {
        const float* q  = (pIss > pClamp) ? pClamp : pIss;
        const float* qt = q + f * 8;
        const uint32_t a = rsb + issB + (uint32_t)(f << 5);
        cpa16(a,       qt);
        cpa16(a + 16u, qt + 4);
        if (issB == 0) {                          // mirror rows 0..7
            const uint32_t m = rsb + kRLb + (uint32_t)(f << 5);
            cpa16(m,       qt);
            cpa16(m + 16u, qt + 4);
        }
        cpcommit();
        pIss += 8 * kF;
        issB += 2560u; if (issB == kRLb) issB = 0;
    };
    auto issue32 = [&]() { issue8(); issue8(); issue8(); issue8(); };

    // prologue: 8 subcommits (64 rows) in flight
    #pragma unroll 1
    for (int g = 0; g < 8; ++g) issue8();

    float s = 0.f, ss = 0.f, mean = 0.f, qss = 0.f;
    float* po = out + (size_t)b * kT * kF + f;
    int nSteady;

    if (c == 0) {
        // groups 0..2: rows 0..95 accumulate
        #pragma unroll 1
        for (int g = 0; g < 3; ++g) {
            cpwait4(); __syncthreads();
            const float* rv = ring + vnF + f;
            #pragma unroll
            for (int u = 0; u < kGR; ++u) {
                float v = rv[u * kF]; s += v; ss = __fmaf_rn(v, v, ss);
            }
            vnF += kGf; issue32();
        }
        // group 3: rows 96..127
        {
            cpwait4(); __syncthreads();
            const float* rv = ring + vnF + f;
            #pragma unroll
            for (int u = 0; u < 4; ++u) {          // rows 96..99
                float v = rv[u * kF]; s += v; ss = __fmaf_rn(v, v, ss);
            }
            const float inv = 1.0f / (float)kMin;  // burst rows 0..99
            const float m0  = s * inv;
            const float vr0 = __fmaf_rn(-m0, m0, ss * inv);
            const float rs0 = rsqrtf(vr0);
            #pragma unroll 4
            for (int t = 0; t < kMin; ++t) {
                float v = ring[t * kF + f];
                __stcs(po + t * kF, (v - m0) * rs0);
            }
            float n = 100.0f;
            #pragma unroll
            for (int u = 4; u < kGR; ++u) {        // rows 100..127 growing
                float v = rv[u * kF]; s += v; ss = __fmaf_rn(v, v, ss);
                n += 1.0f;
                float inv2 = __fdividef(1.0f, n);
                float m    = s * inv2;
                float var  = __fmaf_rn(-m, m, ss * inv2);
                __stcs(po + (96 + u) * kF, (v - m) * rsqrtf(var));
            }
            vnF += kGf; issue32();
        }
        // groups 4..17: rows 128..575 growing
        po += 128 * kF;
        float n = 128.0f;
        #pragma unroll 1
        for (int g = 4; g < 18; ++g) {
            cpwait4(); __syncthreads();
            const float* rv = ring + vnF + f;
            #pragma unroll
            for (int u = 0; u < kGR; ++u) {
                float v = rv[u * kF]; s += v; ss = __fmaf_rn(v, v, ss);
                n += 1.0f;
                float inv = __fdividef(1.0f, n);
                float m   = s * inv;
                float var = __fmaf_rn(-m, m, ss * inv);
                __stcs(po + u * kF, (v - m) * rsqrtf(var));
            }
            vnF += kGf; po += kGf; issue32();
        }
        // group 18: rows 576..607 (transition at t=600)
        {
            cpwait4(); __syncthreads();
            const float* rv = ring + vnF + f;
            #pragma unroll
            for (int u = 0; u < 24; ++u) {         // rows 576..599 growing
                float v = rv[u * kF]; s += v; ss = __fmaf_rn(v, v, ss);
                n += 1.0f;
                float inv = __fdividef(1.0f, n);
                float m   = s * inv;
                float var = __fmaf_rn(-m, m, ss * inv);
                __stcs(po + u * kF, (v - m) * rsqrtf(var));
            }
            mean = s * kInvW; qss = ss * kInvW;
            #pragma unroll
            for (int u = 24; u < kGR; ++u) {       // rows 600..607 steady-1
                float vn = rv[u * kF];
                float vo = (u == 24) ? 0.0f : ring[(u - 25) * kF + f];
                float t1 = (vn - vo) * kInvW;
                mean += t1;
                qss   = __fmaf_rn(t1, vn + vo, qss);
                float var = __fmaf_rn(-mean, mean, qss);
                __stcs(po + u * kF, (vn - mean) * rsqrtf(var));
            }
            vnF += kGf; issue32();                 // vnF = 608*kF
        }
        nSteady = (kL - 608) / kGR;                // 189
    } else {
        // warmup group 0: rows t0+7 .. t0+31 (start-601 .. start-577)
        {
            cpwait4(); __syncthreads();
            const float* rv = ring + vnF + f;
            #pragma unroll
            for (int u = 7; u < kGR; ++u) {
                float v = rv[u * kF]; s += v; ss = __fmaf_rn(v, v, ss);
            }
            vnF += kGf; if (vnF == kRLf) vnF = 0;
            issue32();
        }
        // warmup groups 1..18: 576 rows
        #pragma unroll 1
        for (int g = 1; g < 19; ++g) {
            cpwait4(); __syncthreads();
            const float* rv = ring + vnF + f;
            #pragma unroll
            for (int u = 0; u < kGR; ++u) {
                float v = rv[u * kF]; s += v; ss = __fmaf_rn(v, v, ss);
            }
            vnF += kGf; if (vnF == kRLf) vnF = 0;
            issue32();
        }
        mean = s * kInvW; qss = ss * kInvW;
        nSteady = (end - start) / kGR;             // 208 or 211
    }

    // ---- steady sliding loop ----
    const int g0row = (c == 0) ? 608 : start;
    float* po2 = out + (size_t)b * kT * kF + (size_t)g0row * kF + f;
    #pragma unroll 1
    for (int g = 0; g < nSteady; ++g) {
        cpwait4(); __syncthreads();
        const float* rvn = ring + vnF + f;
        int voF = vnF + kVOf;                      // slot (t-601), group-aligned
        if (voF >= kRLf) voF -= kRLf;              // one wrap check / 32 rows
        const float* rvo = ring + voF + f;         // mirror covers straddle
        #pragma unroll
        for (int u = 0; u < kGR; ++u) {
            float vn = rvn[u * kF];
            float vo = rvo[u * kF];
            float t1 = (vn - vo) * kInvW;
            mean += t1;
            qss   = __fmaf_rn(t1, vn + vo, qss);
            float var = __fmaf_rn(-mean, mean, qss);
            __stcs(po2 + u * kF, (vn - mean) * rsqrtf(var));
        }
        vnF += kGf; if (vnF == kRLf) vnF = 0;
        po2 += kGf;
        issue32();
    }
}

extern "C" void kernel_launch(void* const* d_in, const int* in_sizes, int n_in,
                              void* d_out, int out_size)
{
    const float* x = (const float*)d_in[0];
    float* o = (float*)d_out;
    (void)in_sizes; (void)n_in; (void)out_size;

    cudaFuncSetAttribute(cmn_kernel,
                         cudaFuncAttributeMaxDynamicSharedMemorySize, (int)kSmemB);
    cmn_kernel<<<kGrid, kF, kSmemB>>>(x, o);
}

// round 13
// speedup vs baseline: 1.1869x; 1.1536x over previous
#include <cuda_runtime.h>
#include <cstdint>

// SlidingWindowCmn (16, 60000, 80) fp32, window=600, min=100, center=False,
// norm_vars=True.
// R6 architecture: distributed 16B cp.async -> 704-row SMEM ring (+8 mirror)
// -> per-thread sliding window (1 thread/feature), 16-row commit groups,
// lead = 5 groups. Steady loop processes TWO 16-row groups per
// wait_group(3)+__syncthreads, with a compiler fence between the halves to
// keep them as separate scheduling blocks (R12 lesson: one fused 32-row
// block -> 102 regs). Overwrite-safety (issue-after-consume per half):
// issue #1 overwrites slot-rows R-624..R-609, body #2 vo reads R-585..R-570,
// issue #2 overwrites R-608..R-593, next-iter vo reads R-569.. (disjoint).

namespace {
constexpr int kB      = 16;
constexpr int kT      = 60000;
constexpr int kF      = 80;
constexpr int kWin    = 600;
constexpr int kMin    = 100;
constexpr int kChunks = 9;
constexpr int kL      = 6656;               // 32-mult; last chunk 6752
constexpr int kRL     = 704;                // logical ring rows
constexpr int kRLf    = kRL * kF;           // 56320 floats
constexpr uint32_t kRLb = kRL * 320u;       // 225280 bytes (logical)
constexpr uint32_t kSmemB = (kRL + 8) * 320u;   // 227840 bytes (+8 mirror)
constexpr int kVOf    = (kRL - kWin - 1) * kF;  // 103 rows -> 8240 floats
constexpr float kInvW = 1.0f / 601.0f;
constexpr int kGrid   = kB * kChunks;       // 144
}

__device__ __forceinline__ uint32_t smem_u32(const void* p) {
    uint32_t a;
    asm("{ .reg .u64 t; cvta.to.shared.u64 t, %1; cvt.u32.u64 %0, t; }"
        : "=r"(a) : "l"(p));
    return a;
}
__device__ __forceinline__ void cpa16(uint32_t s, const float* g) {
    asm volatile("cp.async.cg.shared.global [%0], [%1], 16;" :: "r"(s), "l"(g));
}
__device__ __forceinline__ void cpcommit() {
    asm volatile("cp.async.commit_group;" ::: "memory");
}
__device__ __forceinline__ void cpwait4() {
    asm volatile("cp.async.wait_group 4;" ::: "memory");
}
__device__ __forceinline__ void cpwait3() {
    asm volatile("cp.async.wait_group 3;" ::: "memory");
}

__global__ void __launch_bounds__(kF, 1)
cmn_kernel(const float* __restrict__ x, float* __restrict__ out)
{
    extern __shared__ float ring[];
    const int f = threadIdx.x;                    // feature 0..79
    const int c = blockIdx.x % kChunks;
    const int b = blockIdx.x / kChunks;

    const float* xb = x + (size_t)b * kT * kF;
    const int start = c * kL;
    const int end   = (c == kChunks - 1) ? kT : start + kL;

    const uint32_t rsb = smem_u32(ring);
    const float* pClamp = x + ((size_t)kB * kT - 16) * kF;  // last full group

    int vnF;                  // consume group float-offset (slot*80)
    uint32_t issB;            // issue group byte-offset
    const float* pIss;
    if (c == 0) {
        vnF = 0; issB = 0; pIss = xb;
    } else {
        const int t0   = start - 608;             // 32-aligned: 7 pad + 601 warmup
        const int slot = t0 % kRL;
        vnF = slot * kF; issB = (uint32_t)slot * 320u;
        pIss = xb + (size_t)t0 * kF;
    }

    auto issue16 = [&]() {
        const float* q  = (pIss > pClamp) ? pClamp : pIss;
        const float* qt = q + f * 4;                         // 16B per thread
        const uint32_t a = rsb + issB + (uint32_t)(f << 4);
        cpa16(a,         qt);
        cpa16(a + 1280u, qt + 320);
        cpa16(a + 2560u, qt + 640);
        cpa16(a + 3840u, qt + 960);
        if (issB == 0) {                          // wrap group: mirror rows 0..7
            const uint32_t m = rsb + kRLb + (uint32_t)(f << 4);
            cpa16(m,         qt);
            cpa16(m + 1280u, qt + 320);
        }
        cpcommit();
        pIss += 16 * kF;
        issB += 5120u; if (issB == kRLb) issB = 0;
    };

    // prologue: 5 groups (80 rows) in flight
    #pragma unroll 1
    for (int g = 0; g < 5; ++g) issue16();

    float s = 0.f, ss = 0.f, mean = 0.f, qss = 0.f;
    float* po = out + (size_t)b * kT * kF + f;
    int nSteady2;             // steady iterations (32 rows each)

    if (c == 0) {
        // groups 0..5: rows 0..95 accumulate
        #pragma unroll 1
        for (int g = 0; g < 6; ++g) {
            cpwait4(); __syncthreads();
            const float* rv = ring + vnF + f;
            #pragma unroll
            for (int u = 0; u < 16; ++u) {
                float v = rv[u * kF]; s += v; ss = __fmaf_rn(v, v, ss);
            }
            vnF += 16 * kF; issue16();
        }
        // group 6: rows 96..111
        {
            cpwait4(); __syncthreads();
            const float* rv = ring + vnF + f;
            #pragma unroll
            for (int u = 0; u < 4; ++u) {          // rows 96..99
                float v = rv[u * kF]; s += v; ss = __fmaf_rn(v, v, ss);
            }
            const float inv = 1.0f / (float)kMin;  // burst rows 0..99
            const float m0  = s * inv;
            const float vr0 = __fmaf_rn(-m0, m0, ss * inv);
            const float rs0 = rsqrtf(vr0);
            #pragma unroll 4
            for (int t = 0; t < kMin; ++t) {
                float v = ring[t * kF + f];
                __stcs(po + t * kF, (v - m0) * rs0);
            }
            float n = 100.0f;
            #pragma unroll
            for (int u = 4; u < 16; ++u) {         // rows 100..111 growing
                float v = rv[u * kF]; s += v; ss = __fmaf_rn(v, v, ss);
                n += 1.0f;
                float inv2 = __fdividef(1.0f, n);
                float m    = s * inv2;
                float var  = __fmaf_rn(-m, m, ss * inv2);
                __stcs(po + (96 + u) * kF, (v - m) * rsqrtf(var));
            }
            vnF += 16 * kF; issue16();
        }
        // groups 7..36: rows 112..591 growing
        po += 112 * kF;
        float n = 112.0f;
        #pragma unroll 1
        for (int g = 7; g < 37; ++g) {
            cpwait4(); __syncthreads();
            const float* rv = ring + vnF + f;
            #pragma unroll
            for (int u = 0; u < 16; ++u) {
                float v = rv[u * kF]; s += v; ss = __fmaf_rn(v, v, ss);
                n += 1.0f;
                float inv = __fdividef(1.0f, n);
                float m   = s * inv;
                float var = __fmaf_rn(-m, m, ss * inv);
                __stcs(po + u * kF, (v - m) * rsqrtf(var));
            }
            vnF += 16 * kF; po += 16 * kF; issue16();
        }
        // group 37: rows 592..607 (transition at t=600)
        {
            cpwait4(); __syncthreads();
            const float* rv = ring + vnF + f;
            #pragma unroll
            for (int u = 0; u < 8; ++u) {          // rows 592..599 growing
                float v = rv[u * kF]; s += v; ss = __fmaf_rn(v, v, ss);
                n += 1.0f;
                float inv = __fdividef(1.0f, n);
                float m   = s * inv;
                float var = __fmaf_rn(-m, m, ss * inv);
                __stcs(po + u * kF, (v - m) * rsqrtf(var));
            }
            mean = s * kInvW; qss = ss * kInvW;
            #pragma unroll
            for (int u = 8; u < 16; ++u) {         // rows 600..607 steady-1
                float vn = rv[u * kF];
                float vo = (u == 8) ? 0.0f : ring[(u - 9) * kF + f];
                float t1 = (vn - vo) * kInvW;
                mean += t1;
                qss   = __fmaf_rn(t1, vn + vo, qss);
                float var = __fmaf_rn(-mean, mean, qss);
                __stcs(po + u * kF, (vn - mean) * rsqrtf(var));
            }
            vnF += 16 * kF; issue16();             // vnF = 608*kF
        }
        nSteady2 = (kL - 608) / 32;                // 189
    } else {
        // warmup group 0: rows t0+7 .. t0+15 (start-601 .. start-593)
        {
            cpwait4(); __syncthreads();
            const float* rv = ring + vnF + f;
            #pragma unroll
            for (int u = 7; u < 16; ++u) {
                float v = rv[u * kF]; s += v; ss = __fmaf_rn(v, v, ss);
            }
            vnF += 16 * kF; if (vnF == kRLf) vnF = 0;
            issue16();
        }
        // warmup groups 1..37: 592 rows
        #pragma unroll 1
        for (int g = 1; g < 38; ++g) {
            cpwait4(); __syncthreads();
            const float* rv = ring + vnF + f;
            #pragma unroll
            for (int u = 0; u < 16; ++u) {
                float v = rv[u * kF]; s += v; ss = __fmaf_rn(v, v, ss);
            }
            vnF += 16 * kF; if (vnF == kRLf) vnF = 0;
            issue16();
        }
        mean = s * kInvW; qss = ss * kInvW;
        nSteady2 = (end - start) / 32;             // 208 or 211
    }

    // ---- steady: two 16-row groups per wait+barrier ----
    const int g0row = (c == 0) ? 608 : start;
    float* po2 = out + (size_t)b * kT * kF + (size_t)g0row * kF + f;
    #pragma unroll 1
    for (int g = 0; g < nSteady2; ++g) {
        cpwait3(); __syncthreads();               // 2 oldest groups resident
        // --- half 1: rows base..base+15 ---
        {
            const float* rvn = ring + vnF + f;
            int voF = vnF + kVOf; if (voF >= kRLf) voF -= kRLf;
            const float* rvo = ring + voF + f;
            #pragma unroll
            for (int u = 0; u < 16; ++u) {
                float vn = rvn[u * kF];
                float vo = rvo[u * kF];
                float t1 = (vn - vo) * kInvW;
                mean += t1;
                qss   = __fmaf_rn(t1, vn + vo, qss);
                float var = __fmaf_rn(-mean, mean, qss);
                __stcs(po2 + u * kF, (vn - mean) * rsqrtf(var));
            }
            vnF += 16 * kF; if (vnF == kRLf) vnF = 0;
            po2 += 16 * kF;
            issue16();
        }
        asm volatile("" ::: "memory");            // keep halves separate
        // --- half 2: rows base+16..base+31 ---
        {
            const float* rvn = ring + vnF + f;
            int voF = vnF + kVOf; if (voF >= kRLf) voF -= kRLf;
            const float* rvo = ring + voF + f;
            #pragma unroll
            for (int u = 0; u < 16; ++u) {
                float vn = rvn[u * kF];
                float vo = rvo[u * kF];
                float t1 = (vn - vo) * kInvW;
                mean += t1;
                qss   = __fmaf_rn(t1, vn + vo, qss);
                float var = __fmaf_rn(-mean, mean, qss);
                __stcs(po2 + u * kF, (vn - mean) * rsqrtf(var));
            }
            vnF += 16 * kF; if (vnF == kRLf) vnF = 0;
            po2 += 16 * kF;
            issue16();
        }
    }
}

extern "C" void kernel_launch(void* const* d_in, const int* in_sizes, int n_in,
                              void* d_out, int out_size)
{
    const float* x = (const float*)d_in[0];
    float* o = (float*)d_out;
    (void)in_sizes; (void)n_in; (void)out_size;

    cudaFuncSetAttribute(cmn_kernel,
                         cudaFuncAttributeMaxDynamicSharedMemorySize, (int)kSmemB);
    cmn_kernel<<<kGrid, kF, kSmemB>>>(x, o);
}